// round 14
// baseline (speedup 1.0000x reference)
#include <cuda_runtime.h>
#include <cuda_fp16.h>
#include <math.h>

#define TT 256
#define BB 64
#define HH 1024
#define G4 4096
#define OUT_Y ((size_t)TT * BB * 2 * HH)

typedef unsigned int u32;

// ---------------- scratch ----------------
__device__ __half g_pre16[(size_t)2 * TT * BB * G4];       // 256MB
__device__ __half g_h16[2][2][BB * HH];                    // ping-pong h (fp16)
__device__ __half g_Wih16[(size_t)2 * G4 * HH];
__device__ __half g_Whh16[(size_t)2 * G4 * HH];
__device__ __half g_x16[(size_t)TT * BB * HH];
__device__ unsigned int g_bar2[2];

// ---------------- PTX helpers ----------------
__device__ __forceinline__ u32 s2u(const void* p) {
    u32 a;
    asm("{ .reg .u64 t; cvta.to.shared.u64 t, %1; cvt.u32.u64 %0, t; }" : "=r"(a) : "l"(p));
    return a;
}
__device__ __forceinline__ void cpa16(u32 d, const void* s) {
    asm volatile("cp.async.cg.shared.global [%0], [%1], 16;" :: "r"(d), "l"(s));
}
#define CP_COMMIT asm volatile("cp.async.commit_group;" ::: "memory")
#define CP_WAIT1  asm volatile("cp.async.wait_group 1;" ::: "memory")

__device__ __forceinline__ void ldsm4(u32& r0, u32& r1, u32& r2, u32& r3, u32 a) {
    asm volatile("ldmatrix.sync.aligned.m8n8.x4.shared.b16 {%0,%1,%2,%3}, [%4];"
                 : "=r"(r0), "=r"(r1), "=r"(r2), "=r"(r3) : "r"(a));
}
__device__ __forceinline__ void mma16816(float* c, const u32* a, const u32* b) {
    asm volatile(
        "mma.sync.aligned.m16n8k16.row.col.f32.f16.f16.f32 "
        "{%0,%1,%2,%3}, {%4,%5,%6,%7}, {%8,%9}, {%0,%1,%2,%3};"
        : "+f"(c[0]), "+f"(c[1]), "+f"(c[2]), "+f"(c[3])
        : "r"(a[0]), "r"(a[1]), "r"(a[2]), "r"(a[3]), "r"(b[0]), "r"(b[1]));
}
__device__ __forceinline__ u32 ld_acq(const unsigned int* p) {
    u32 v;
    asm volatile("ld.acquire.gpu.u32 %0, [%1];" : "=r"(v) : "l"(p) : "memory");
    return v;
}
__device__ __forceinline__ void red_release_add(unsigned int* p, u32 v) {
    asm volatile("red.release.gpu.global.add.u32 [%0], %1;" :: "l"(p), "r"(v) : "memory");
}
// fast sigmoid/tanh via MUFU (err ~1e-6, independent of harness math flags)
__device__ __forceinline__ float fsig(float x) {
    float t, r;
    asm("ex2.approx.ftz.f32 %0, %1;" : "=f"(t) : "f"(-x * 1.442695041f));
    asm("rcp.approx.ftz.f32 %0, %1;" : "=f"(r) : "f"(1.f + t));
    return r;
}
__device__ __forceinline__ float ftanh(float x) {
    float t, r;
    asm("ex2.approx.ftz.f32 %0, %1;" : "=f"(t) : "f"(x * 2.885390082f));  // e^{2x}
    asm("rcp.approx.ftz.f32 %0, %1;" : "=f"(r) : "f"(1.f + t));
    return 1.f - 2.f * r;
}

// ============================================================
// Fused prep: all fp32->fp16 conversions + state init + barrier reset.
// grid = 65792 blocks x 256:
//   [0,32768): weights (4 x 8192)   [32768,65536): x   [65536,65792): init
// ============================================================
__global__ void prep(const float* __restrict__ x, const float* __restrict__ h0,
                     const float* __restrict__ Wihf, const float* __restrict__ Whhf,
                     const float* __restrict__ Wihb, const float* __restrict__ Whhb)
{
    int b = blockIdx.x, tid = threadIdx.x;
    if (b < 32768) {
        int w = b >> 13;
        int i = (b & 8191) * 256 + tid;
        const float* src = (w == 0) ? Wihf : (w == 1) ? Wihb : (w == 2) ? Whhf : Whhb;
        __half* dst = ((w < 2) ? g_Wih16 : g_Whh16) + ((w & 1) ? (size_t)G4 * HH : 0);
        float2 v = ((const float2*)src)[i];
        ((__half2*)dst)[i] = __halves2half2(__float2half_rn(v.x), __float2half_rn(v.y));
    } else if (b < 65536) {
        int i = (b - 32768) * 256 + tid;
        float2 v = ((const float2*)x)[i];
        ((__half2*)g_x16)[i] = __halves2half2(__float2half_rn(v.x), __float2half_rn(v.y));
    } else {
        int i = (b - 65536) * 256 + tid;     // 0..65535 = BB*HH
        if (i < 2) g_bar2[i] = 0;
        __half hb = __float2half_rn(h0[i]);
        g_h16[0][0][i] = hb; g_h16[1][0][i] = hb;
    }
}

// ============================================================
// Precompute: g_pre16 = fp16(x16 @ W_ih16^T + b_ih + b_hh)
// Block: M=128 rows (r=b*T+t), N=128 gate cols, K=1024 (32 stages of 32).
// ============================================================
#define PC_STAGE 20480
__global__ __launch_bounds__(256, 2) void precompute_mma(
    const float* __restrict__ bihf, const float* __restrict__ bhhf,
    const float* __restrict__ bihb, const float* __restrict__ bhhb)
{
    extern __shared__ char smem[];
    const u32 smem_u = s2u(smem);
    const int tid = threadIdx.x, lane = tid & 31, wid = tid >> 5;
    const int wm = wid >> 2, wn = wid & 3;
    const int c0 = blockIdx.x * 128, r0 = blockIdx.y * 128, dir = blockIdx.z;

    const __half* __restrict__ Ax = g_x16 + (size_t)r0 * HH;
    const __half* __restrict__ Bw = g_Wih16 + ((size_t)dir * G4 + c0) * HH;

    float acc[4][4][4];
#pragma unroll
    for (int mi = 0; mi < 4; mi++)
#pragma unroll
        for (int nj = 0; nj < 4; nj++)
#pragma unroll
            for (int q = 0; q < 4; q++) acc[mi][nj][q] = 0.f;

#define PC_LOAD(st, buf) do { \
    int ko_ = (st) * 32; \
    u32 ab_ = smem_u + (buf) * PC_STAGE; \
    _Pragma("unroll") \
    for (int it = 0; it < 2; it++) { \
        int id = it * 256 + tid, row = id >> 2, c = id & 3; \
        cpa16(ab_ + row * 80 + c * 16, Ax + (size_t)row * HH + ko_ + c * 8); \
    } \
    u32 bb_ = ab_ + 10240; \
    _Pragma("unroll") \
    for (int it = 0; it < 2; it++) { \
        int id = it * 256 + tid, row = id >> 2, c = id & 3; \
        cpa16(bb_ + row * 80 + c * 16, Bw + (size_t)row * HH + ko_ + c * 8); \
    } \
} while (0)

    PC_LOAD(0, 0); CP_COMMIT;
    PC_LOAD(1, 1); CP_COMMIT;
    for (int st = 0; st < 32; st++) {
        CP_WAIT1;
        __syncthreads();
        if (st + 2 < 32) { int bf = (st + 2) % 3; PC_LOAD(st + 2, bf); }
        CP_COMMIT;
        const u32 abase = smem_u + (st % 3) * PC_STAGE;
        const u32 bbase = abase + 10240;
#pragma unroll
        for (int kk = 0; kk < 2; kk++) {
            u32 a[4][4];
#pragma unroll
            for (int mi = 0; mi < 4; mi++) {
                int row = wm * 64 + mi * 16 + (lane & 15);
                ldsm4(a[mi][0], a[mi][1], a[mi][2], a[mi][3],
                      abase + row * 80 + kk * 32 + (lane >> 4) * 16);
            }
            u32 b_[4][2];
#pragma unroll
            for (int nj2 = 0; nj2 < 2; nj2++) {
                int row = wn * 32 + nj2 * 16 + (lane & 7) + ((lane >> 4) << 3);
                u32 r0v, r1v, r2v, r3v;
                ldsm4(r0v, r1v, r2v, r3v,
                      bbase + row * 80 + kk * 32 + ((lane >> 3) & 1) * 16);
                b_[nj2 * 2][0] = r0v; b_[nj2 * 2][1] = r1v;
                b_[nj2 * 2 + 1][0] = r2v; b_[nj2 * 2 + 1][1] = r3v;
            }
#pragma unroll
            for (int mi = 0; mi < 4; mi++)
#pragma unroll
                for (int nj = 0; nj < 4; nj++)
                    mma16816(acc[mi][nj], a[mi], b_[nj]);
        }
    }
#undef PC_LOAD

    const float* bi = dir ? bihb : bihf;
    const float* bh = dir ? bhhb : bhhf;
#pragma unroll
    for (int nj = 0; nj < 4; nj++) {
        int n = c0 + wn * 32 + nj * 8 + (lane & 3) * 2;
        float bz0 = bi[n] + bh[n];
        float bz1 = bi[n + 1] + bh[n + 1];
#pragma unroll
        for (int mi = 0; mi < 4; mi++)
#pragma unroll
            for (int hrow = 0; hrow < 2; hrow++) {
                int m = wm * 64 + mi * 16 + (lane >> 2) + hrow * 8;
                int r = r0 + m, t = r & (TT - 1), bb2 = r >> 8;
                __half* dst = g_pre16 + (((size_t)dir * TT + t) * BB + bb2) * G4 + n;
                *(__half2*)dst = __halves2half2(
                    __float2half_rn(acc[mi][nj][hrow * 2 + 0] + bz0),
                    __float2half_rn(acc[mi][nj][hrow * 2 + 1] + bz1));
            }
    }
}

// ============================================================
// Persistent fused LSTM. 128 CTAs (64 j-tiles x 2 dirs), 1/SM.
// W_hh slice RESIDENT in smem. Step GEMM: 4-way K-split, warp tile
// M32 x N64 (wk=wid>>1 k-quarter, wm=wid&1): per 16k, 6 ldsm feed 16 mma
// (1.5 ldsm / 4 mma) — LSU-issue diet. 4 partial tiles folded in pointwise.
// Partials: q0->gatesA, q1..3 -> dead A pipeline buffers.
// smem: W 132096 | A 3x17408 (dbl as gatesB/C/D) | gatesA | pre 2x
// ============================================================
#define W_STR 2064
#define A_OFF 132096
#define A_STAGE 17408
#define GATES_OFF 184320
#define PRE_OFF 201728
#define PRE_BUF 9216
#define ST_SMEM 220160

__global__ __launch_bounds__(256, 1) void step_persist(
    const int* __restrict__ mask, const float* __restrict__ h0,
    float* __restrict__ out)
{
    extern __shared__ char smem[];
    const u32 smem_u = s2u(smem);
    const int tid = threadIdx.x, lane = tid & 31, wid = tid >> 5;
    const int wk = wid >> 1;            // k-quarter (0..3)
    const int wm = wid & 1;             // M-half (M32)
    const int j0 = blockIdx.x * 16, dir = blockIdx.y;

    // ---- load resident W (64 gate-cols x 1024 k fp16) + pre(0) ----
    {
        const __half* W = g_Whh16 + (size_t)dir * G4 * HH;
#pragma unroll
        for (int it = 0; it < 32; it++) {
            int id = it * 256 + tid;
            int row = id >> 7, c = id & 127;       // row: gate-col, c: 16B chunk
            int grp = row >> 4, jj = row & 15;
            cpa16(smem_u + row * W_STR + c * 16,
                  W + (size_t)(grp * HH + j0 + jj) * HH + c * 8);
        }
        // pre(0) into buf 0
        int t0 = dir ? (TT - 1) : 0;
        const __half* pg = g_pre16 + ((size_t)dir * TT + t0) * BB * G4;
#pragma unroll
        for (int it = 0; it < 2; it++) {
            int id = it * 256 + tid;
            int b = id >> 3, seg = (id >> 1) & 3, q = id & 1;
            cpa16(smem_u + PRE_OFF + b * 144 + seg * 32 + q * 16,
                  pg + (size_t)b * G4 + seg * HH + j0 + q * 8);
        }
        CP_COMMIT;
    }

    // ---- per-thread persistent state ----
    float h0c[4], creg[4];
#pragma unroll
    for (int it = 0; it < 4; it++) {
        int id = it * 256 + tid;
        int b = id >> 4, jj = id & 15;
        h0c[it] = h0[b * HH + j0 + jj];
        creg[it] = h0c[it];
    }

    // partial-gate buffers: q=0 -> gatesA; q=1..3 -> A pipeline bufs 0..2
    float* gbufs[4];
    gbufs[0] = (float*)(smem + GATES_OFF);
    gbufs[1] = (float*)(smem + A_OFF);
    gbufs[2] = (float*)(smem + A_OFF + A_STAGE);
    gbufs[3] = (float*)(smem + A_OFF + 2 * A_STAGE);

    for (int s = 0; s < TT; s++) {
        const int pp = s & 1;
        const int t = dir ? (TT - 1 - s) : s;
        const __half* __restrict__ Ah = g_h16[dir][pp];
        const __half* presm = (const __half*)(smem + PRE_OFF + (s & 1) * PRE_BUF);

        float acc[2][8][4];
#pragma unroll
        for (int mi = 0; mi < 2; mi++)
#pragma unroll
            for (int nj = 0; nj < 8; nj++)
#pragma unroll
                for (int q = 0; q < 4; q++) acc[mi][nj][q] = 0.f;

#define ST_LOAD(st, buf) do { \
    int ko_ = (st) * 128; \
    u32 ab_ = smem_u + A_OFF + (buf) * A_STAGE; \
    _Pragma("unroll") \
    for (int it = 0; it < 4; it++) { \
        int id = it * 256 + tid, row = id >> 4, c = id & 15; \
        cpa16(ab_ + row * 272 + c * 16, Ah + (size_t)row * HH + ko_ + c * 8); \
    } \
} while (0)

        ST_LOAD(0, 0); CP_COMMIT;
        ST_LOAD(1, 1); CP_COMMIT;

        // mask prefetch into regs (issues early, consumed at pointwise)
        float mreg[4];
#pragma unroll
        for (int it = 0; it < 4; it++) {
            int id = it * 256 + tid, b = id >> 4;
            mreg[it] = (float)__ldg(&mask[b * TT + t]);
        }

        for (int st = 0; st < 8; st++) {
            CP_WAIT1;
            __syncthreads();
            if (st + 2 < 8) { int bf = (st + 2) % 3; ST_LOAD(st + 2, bf); }
            if (st == 0 && s + 1 < TT) {
                // prefetch pre(s+1) into the other buffer (rides this group)
                int tn = dir ? (TT - 2 - s) : (s + 1);
                const __half* pg = g_pre16 + ((size_t)dir * TT + tn) * BB * G4;
                u32 pb = smem_u + PRE_OFF + ((s + 1) & 1) * PRE_BUF;
#pragma unroll
                for (int it = 0; it < 2; it++) {
                    int id = it * 256 + tid;
                    int b = id >> 3, seg = (id >> 1) & 3, q = id & 1;
                    cpa16(pb + b * 144 + seg * 32 + q * 16,
                          pg + (size_t)b * G4 + seg * HH + j0 + q * 8);
                }
            }
            CP_COMMIT;
            // this warp's k-window within the stage: 32k starting at wk*32
            const u32 abase = smem_u + A_OFF + (st % 3) * A_STAGE + wk * 64;
            const u32 wbase = smem_u + st * 256 + wk * 64;
#pragma unroll
            for (int kk = 0; kk < 2; kk++) {        // 2 x 16k per quarter
                u32 a[2][4];
#pragma unroll
                for (int mi = 0; mi < 2; mi++) {
                    int row = wm * 32 + mi * 16 + (lane & 15);
                    ldsm4(a[mi][0], a[mi][1], a[mi][2], a[mi][3],
                          abase + row * 272 + kk * 32 + (lane >> 4) * 16);
                }
                u32 b_[8][2];
#pragma unroll
                for (int nj2 = 0; nj2 < 4; nj2++) {
                    int row = nj2 * 16 + (lane & 7) + ((lane >> 4) << 3);
                    u32 r0, r1, r2, r3;
                    ldsm4(r0, r1, r2, r3,
                          wbase + row * W_STR + kk * 32 + ((lane >> 3) & 1) * 16);
                    b_[nj2 * 2][0] = r0; b_[nj2 * 2][1] = r1;
                    b_[nj2 * 2 + 1][0] = r2; b_[nj2 * 2 + 1][1] = r3;
                }
#pragma unroll
                for (int mi = 0; mi < 2; mi++)
#pragma unroll
                    for (int nj = 0; nj < 8; nj++)
                        mma16816(acc[mi][nj], a[mi], b_[nj]);   // h16 * W16
            }
        }
#undef ST_LOAD

        // ---- write partial gate tiles (k-quarter wk -> gbufs[wk]) ----
        __syncthreads();   // all A-buffer reads done before reuse as gates
        {
            float* gbuf = gbufs[wk];
#pragma unroll
            for (int nj = 0; nj < 8; nj++) {
                int n = nj * 8 + (lane & 3) * 2;
#pragma unroll
                for (int mi = 0; mi < 2; mi++) {
                    int m = wm * 32 + mi * 16 + (lane >> 2);
                    *(float2*)&gbuf[m * 68 + n] =
                        make_float2(acc[mi][nj][0], acc[mi][nj][1]);
                    *(float2*)&gbuf[(m + 8) * 68 + n] =
                        make_float2(acc[mi][nj][2], acc[mi][nj][3]);
                }
            }
        }
        __syncthreads();

        // ---- pointwise: 4 outputs/thread; write h (needed by others) first ----
        float hnv[4];
#pragma unroll
        for (int it = 0; it < 4; it++) {
            int id = it * 256 + tid;
            int b = id >> 4, jj = id & 15;
            int j = j0 + jj;
            float gi = __half2float(presm[b * 72 + jj]);
            float gf = __half2float(presm[b * 72 + 16 + jj]);
            float gg = __half2float(presm[b * 72 + 32 + jj]);
            float go = __half2float(presm[b * 72 + 48 + jj]);
#pragma unroll
            for (int q = 0; q < 4; q++) {
                gi += gbufs[q][b * 68 + jj];
                gf += gbufs[q][b * 68 + 16 + jj];
                gg += gbufs[q][b * 68 + 32 + jj];
                go += gbufs[q][b * 68 + 48 + jj];
            }
            float iv = fsig(gi);
            float fv = fsig(gf);
            float gv = ftanh(gg);
            float ov = fsig(go);
            float cn = fv * creg[it] + iv * gv;
            float hn = ov * ftanh(cn);
            float m = mreg[it];
            float hz = h0c[it];
            hn = hn * m + hz * (1.f - m);
            cn = cn * m + hz * (1.f - m);
            creg[it] = cn;
            hnv[it] = hn;
            g_h16[dir][pp ^ 1][b * HH + j] = __float2half_rn(hn);
        }

        // ---- release h, arrive on per-dir barrier (release-atomic) ----
        __syncthreads();
        if (tid == 0) red_release_add(&g_bar2[dir], 1u);

        // ---- deferred output writes (overlap other CTAs' arrival) ----
#pragma unroll
        for (int it = 0; it < 4; it++) {
            int id = it * 256 + tid;
            int b = id >> 4, jj = id & 15;
            int j = j0 + jj;
            // outputs stacked in ITERATION order for both directions (per reference)
            out[((size_t)s * BB + b) * (2 * HH) + (size_t)dir * HH + j] = hnv[it];
            if (s == TT - 1) {
                out[OUT_Y + (size_t)b * (2 * HH) + (size_t)dir * HH + j] = hnv[it];
                out[OUT_Y + (size_t)BB * 2 * HH + (size_t)b * (2 * HH) + (size_t)dir * HH + j] = creg[it];
            }
        }

        if (s < TT - 1) {
            if (tid == 0) {
                unsigned int target = 64u * (s + 1);
                while (ld_acq(&g_bar2[dir]) < target) { }
            }
            __syncthreads();
        }
    }
}

// ---------------- host ----------------
extern "C" void kernel_launch(void* const* d_in, const int* in_sizes, int n_in,
                              void* d_out, int out_size) {
    const float* x    = (const float*)d_in[0];
    const int*   mask = (const int*)  d_in[1];
    const float* h0   = (const float*)d_in[2];
    const float* Wihf = (const float*)d_in[3];
    const float* Whhf = (const float*)d_in[4];
    const float* bihf = (const float*)d_in[5];
    const float* bhhf = (const float*)d_in[6];
    const float* Wihb = (const float*)d_in[7];
    const float* Whhb = (const float*)d_in[8];
    const float* bihb = (const float*)d_in[9];
    const float* bhhb = (const float*)d_in[10];
    float* out = (float*)d_out;

    cudaFuncSetAttribute(precompute_mma, cudaFuncAttributeMaxDynamicSharedMemorySize, 3 * PC_STAGE);
    cudaFuncSetAttribute(step_persist,   cudaFuncAttributeMaxDynamicSharedMemorySize, ST_SMEM);

    prep<<<65792, 256>>>(x, h0, Wihf, Whhf, Wihb, Whhb);
    precompute_mma<<<dim3(32, 128, 2), 256, 3 * PC_STAGE>>>(bihf, bhhf, bihb, bhhb);
    step_persist<<<dim3(64, 2), 256, ST_SMEM>>>(mask, h0, out);
}